// round 2
// baseline (speedup 1.0000x reference)
#include <cuda_runtime.h>
#include <math.h>

#define D    1280
#define H    20
#define HDIM 64
#define TQ   64
#define TK   32

// Scratch (allocation-free): sized for the fixed problem shapes.
__device__ float g_q[1600 * 1280];
__device__ float g_kv[6000 * 2560];
__device__ float g_attn[1600 * 1280];

// ---------------------------------------------------------------------------
// Tiled SGEMM: C[M,N] = (A[M,K] @ B[K,N] + bias[N]) * scale
// BM=BN=128, BK=16, 256 threads, 8x8 per thread.
// ---------------------------------------------------------------------------
__global__ __launch_bounds__(256) void gemm_bias_kernel(
    const float* __restrict__ A, const float* __restrict__ Bm,
    const float* __restrict__ bias, float* __restrict__ C,
    int M, int N, int K, float scale)
{
    __shared__ float As[16][128];   // transposed A tile: As[k][m]
    __shared__ float Bs[16][128];   // Bs[k][n]

    int tid = threadIdx.x;
    int tx = tid & 15, ty = tid >> 4;
    int brow = blockIdx.y * 128;
    int bcol = blockIdx.x * 128;

    float acc[8][8];
    #pragma unroll
    for (int i = 0; i < 8; i++)
        #pragma unroll
        for (int j = 0; j < 8; j++) acc[i][j] = 0.f;

    for (int k0 = 0; k0 < K; k0 += 16) {
        // Load A tile (128x16) as float4, store transposed.
        #pragma unroll
        for (int t = 0; t < 2; t++) {
            int s = tid + t * 256;          // 0..511 float4 slots
            int r = s >> 2;                  // 0..127
            int c = (s & 3) << 2;            // 0,4,8,12
            float4 v = make_float4(0.f, 0.f, 0.f, 0.f);
            int ga = brow + r;
            if (ga < M)
                v = *reinterpret_cast<const float4*>(A + (size_t)ga * K + k0 + c);
            As[c + 0][r] = v.x;
            As[c + 1][r] = v.y;
            As[c + 2][r] = v.z;
            As[c + 3][r] = v.w;
        }
        // Load B tile (16x128) as float4.
        #pragma unroll
        for (int t = 0; t < 2; t++) {
            int s = tid + t * 256;
            int r = s >> 5;                  // 0..15
            int c = (s & 31) << 2;           // 0..124
            float4 v = make_float4(0.f, 0.f, 0.f, 0.f);
            if (bcol + c < N)
                v = *reinterpret_cast<const float4*>(Bm + (size_t)(k0 + r) * N + bcol + c);
            *reinterpret_cast<float4*>(&Bs[r][c]) = v;
        }
        __syncthreads();

        #pragma unroll
        for (int kk = 0; kk < 16; kk++) {
            float a[8], b[8];
            #pragma unroll
            for (int i = 0; i < 8; i++) a[i] = As[kk][ty * 8 + i];
            #pragma unroll
            for (int j = 0; j < 8; j++) b[j] = Bs[kk][tx * 8 + j];
            #pragma unroll
            for (int i = 0; i < 8; i++)
                #pragma unroll
                for (int j = 0; j < 8; j++)
                    acc[i][j] += a[i] * b[j];
        }
        __syncthreads();
    }

    #pragma unroll
    for (int i = 0; i < 8; i++) {
        int r = brow + ty * 8 + i;
        if (r >= M) continue;
        #pragma unroll
        for (int j = 0; j < 8; j++) {
            int cidx = bcol + tx * 8 + j;
            if (cidx < N)
                C[(size_t)r * N + cidx] = (acc[i][j] + bias[cidx]) * scale;
        }
    }
}

// ---------------------------------------------------------------------------
// Flash-style cross attention.
// Block = (head, batch, q-tile of 64). 256 threads (16x16).
// q: [Qlen, D] already scaled. kv: [KVlen, 2D] (K cols [h*64..), V at D+h*64).
// Streams the batch's `enc` KV rows in chunks of TK=32 with online softmax.
// ---------------------------------------------------------------------------
__global__ __launch_bounds__(256) void attn_kernel(
    const float* __restrict__ q, const float* __restrict__ kv,
    const int* __restrict__ seq_lens, float* __restrict__ outbuf,
    int nB, int enc)
{
    __shared__ float Qs[TQ][HDIM + 4];
    __shared__ float Ks[TK][HDIM + 4];
    __shared__ float Vs[TK][HDIM + 4];
    __shared__ float Ps[TQ][TK + 4];

    int h = blockIdx.x;
    int b = blockIdx.y;
    int tile = blockIdx.z;

    int qstart = 0;
    for (int i = 0; i < b; i++) qstart += seq_lens[i];
    int qlen = seq_lens[b];
    if (tile * TQ >= qlen) return;
    int qrow0 = qstart + tile * TQ;
    int rows = min(TQ, qlen - tile * TQ);
    size_t kvbase = (size_t)b * enc;

    int tid = threadIdx.x;
    // Load Q tile (64x64)
    for (int i = tid; i < TQ * HDIM; i += 256) {
        int r = i >> 6, c = i & 63;
        Qs[r][c] = (r < rows) ? q[(size_t)(qrow0 + r) * D + h * HDIM + c] : 0.f;
    }

    int tx = tid & 15, ty = tid >> 4;
    int r0 = ty * 4, c0 = tx * 2, hc = tx * 4;

    float m[4], l[4], O[4][4];
    #pragma unroll
    for (int i = 0; i < 4; i++) {
        m[i] = -1e30f; l[i] = 0.f;
        #pragma unroll
        for (int j = 0; j < 4; j++) O[i][j] = 0.f;
    }
    __syncthreads();

    for (int kc = 0; kc < enc; kc += TK) {
        int kn = min(TK, enc - kc);
        // Load K and V chunks (32x64 each)
        for (int i = tid; i < TK * HDIM; i += 256) {
            int r = i >> 6, c = i & 63;
            float kval = 0.f, vval = 0.f;
            if (r < kn) {
                const float* rowp = kv + (kvbase + kc + r) * (size_t)(2 * D) + h * HDIM;
                kval = rowp[c];
                vval = rowp[D + c];
            }
            Ks[r][c] = kval;
            Vs[r][c] = vval;
        }
        __syncthreads();

        // S = Q @ K^T : per thread 4 rows x 2 key-cols
        float S[4][2];
        #pragma unroll
        for (int i = 0; i < 4; i++) { S[i][0] = 0.f; S[i][1] = 0.f; }
        #pragma unroll 4
        for (int d = 0; d < HDIM; d++) {
            float k0v = Ks[c0][d], k1v = Ks[c0 + 1][d];
            #pragma unroll
            for (int i = 0; i < 4; i++) {
                float qv = Qs[r0 + i][d];
                S[i][0] += qv * k0v;
                S[i][1] += qv * k1v;
            }
        }
        bool v0 = (c0 < kn), v1 = (c0 + 1 < kn);
        #pragma unroll
        for (int i = 0; i < 4; i++) {
            if (!v0) S[i][0] = -1e30f;
            if (!v1) S[i][1] = -1e30f;
        }

        // Online softmax: row max / sum across the 16 tx lanes
        #pragma unroll
        for (int i = 0; i < 4; i++) {
            float mc = fmaxf(S[i][0], S[i][1]);
            #pragma unroll
            for (int off = 1; off < 16; off <<= 1)
                mc = fmaxf(mc, __shfl_xor_sync(0xffffffffu, mc, off));
            float mn = fmaxf(m[i], mc);
            float alpha = __expf(m[i] - mn);
            m[i] = mn;
            float p0 = __expf(S[i][0] - mn);
            float p1 = __expf(S[i][1] - mn);
            Ps[r0 + i][c0] = p0;
            Ps[r0 + i][c0 + 1] = p1;
            float rs = p0 + p1;
            #pragma unroll
            for (int off = 1; off < 16; off <<= 1)
                rs += __shfl_xor_sync(0xffffffffu, rs, off);
            l[i] = l[i] * alpha + rs;
            #pragma unroll
            for (int j = 0; j < 4; j++) O[i][j] *= alpha;
        }
        __syncthreads();

        // O += P @ V : per thread 4 rows x 4 hd-cols
        #pragma unroll 4
        for (int kk = 0; kk < TK; kk++) {
            float vv0 = Vs[kk][hc], vv1 = Vs[kk][hc + 1];
            float vv2 = Vs[kk][hc + 2], vv3 = Vs[kk][hc + 3];
            #pragma unroll
            for (int i = 0; i < 4; i++) {
                float p = Ps[r0 + i][kk];
                O[i][0] += p * vv0;
                O[i][1] += p * vv1;
                O[i][2] += p * vv2;
                O[i][3] += p * vv3;
            }
        }
        __syncthreads();
    }

    #pragma unroll
    for (int i = 0; i < 4; i++) {
        if (r0 + i < rows) {
            float inv = 1.f / l[i];
            #pragma unroll
            for (int j = 0; j < 4; j++)
                outbuf[(size_t)(qrow0 + r0 + i) * D + h * HDIM + hc + j] = O[i][j] * inv;
        }
    }
}

// ---------------------------------------------------------------------------
// kernel_launch: Qproj -> KVproj -> flash attention -> Oproj
// ---------------------------------------------------------------------------
extern "C" void kernel_launch(void* const* d_in, const int* in_sizes, int n_in,
                              void* d_out, int out_size)
{
    const float* hidden = (const float*)d_in[0];
    const float* cross  = (const float*)d_in[1];
    const int*   seqs   = (const int*)d_in[2];
    const float* Wq  = (const float*)d_in[3];
    const float* bq  = (const float*)d_in[4];
    const float* Wkv = (const float*)d_in[5];
    const float* bkv = (const float*)d_in[6];
    const float* Wo  = (const float*)d_in[7];
    const float* bo  = (const float*)d_in[8];
    float* out = (float*)d_out;

    int qlen  = in_sizes[0] / D;
    int kvlen = in_sizes[1] / D;
    int nB    = in_sizes[2];
    int enc   = kvlen / nB;

    float *qbuf, *kvbuf, *abuf;
    cudaGetSymbolAddress((void**)&qbuf, g_q);
    cudaGetSymbolAddress((void**)&kvbuf, g_kv);
    cudaGetSymbolAddress((void**)&abuf, g_attn);

    dim3 blk(256);
    float scaling = 1.0f / sqrtf((float)HDIM);

    // Q projection (scaling fused)
    gemm_bias_kernel<<<dim3(D / 128, (qlen + 127) / 128), blk>>>(
        hidden, Wq, bq, qbuf, qlen, D, D, scaling);

    // KV projection
    gemm_bias_kernel<<<dim3((2 * D) / 128, (kvlen + 127) / 128), blk>>>(
        cross, Wkv, bkv, kvbuf, kvlen, 2 * D, D, 1.0f);

    // Fused attention
    int qtiles = (qlen + TQ - 1) / TQ;
    attn_kernel<<<dim3(H, nB, qtiles), blk>>>(qbuf, kvbuf, seqs, abuf, nB, enc);

    // Output projection
    gemm_bias_kernel<<<dim3(D / 128, (qlen + 127) / 128), blk>>>(
        abuf, Wo, bo, out, qlen, D, D, 1.0f);
}

// round 4
// speedup vs baseline: 1.8193x; 1.8193x over previous
#include <cuda_runtime.h>
#include <math.h>
#include <stdint.h>

#define D    1280
#define H    20
#define HDIM 64
#define TQ   64
#define TK   32

// Scratch (allocation-free): sized for the fixed problem shapes.
__device__ float g_q[1600 * 1280];
__device__ float g_kv[6000 * 2560];
__device__ float g_attn[1600 * 1280];

// ---------------------------------------------------------------------------
// tf32 helpers
// ---------------------------------------------------------------------------
__device__ __forceinline__ float to_tf32(float x) {
    uint32_t y;
    asm("cvt.rna.tf32.f32 %0, %1;" : "=r"(y) : "f"(x));
    return __uint_as_float(y);
}

__device__ __forceinline__ void mma_tf32(float* d, const uint32_t* a, const uint32_t* b) {
    asm volatile(
        "mma.sync.aligned.m16n8k8.row.col.f32.tf32.tf32.f32 "
        "{%0,%1,%2,%3}, {%4,%5,%6,%7}, {%8,%9}, {%0,%1,%2,%3};\n"
        : "+f"(d[0]), "+f"(d[1]), "+f"(d[2]), "+f"(d[3])
        : "r"(a[0]), "r"(a[1]), "r"(a[2]), "r"(a[3]), "r"(b[0]), "r"(b[1]));
}

// ---------------------------------------------------------------------------
// TF32 tensor-core GEMM: C[M,N] = (A[M,K] @ B[K,N] + bias[N]) * scale
// BM=BN=128, BK=32. 256 threads = 8 warps in a 2(M) x 4(N) grid.
// Warp tile 64x32 -> 4x4 m16n8k8 fragments.
// Requires K % 32 == 0, N % 128 == 0 (holds for all three projections).
// ---------------------------------------------------------------------------
__global__ __launch_bounds__(256) void gemm_tf32_kernel(
    const float* __restrict__ A, const float* __restrict__ Bm,
    const float* __restrict__ bias, float* __restrict__ C,
    int M, int N, int K, float scale)
{
    __shared__ float As[128][36];   // [m][k], k padded 32->36 (conflict-free frag reads)
    __shared__ float Bs[32][136];   // [k][n], n padded 128->136

    int tid  = threadIdx.x;
    int wid  = tid >> 5, lane = tid & 31;
    int wm   = wid >> 2, wn = wid & 3;        // 2 x 4 warp grid
    int qr   = lane >> 2, qc = lane & 3;      // quad row/col within warp
    int brow = blockIdx.y * 128;
    int bcol = blockIdx.x * 128;

    int mBase = wm * 64, nBase = wn * 32;

    float acc[4][4][4];
    #pragma unroll
    for (int i = 0; i < 4; i++)
        #pragma unroll
        for (int j = 0; j < 4; j++)
            #pragma unroll
            for (int t = 0; t < 4; t++) acc[i][j][t] = 0.f;

    // Per-thread staging: A tile 128x32 -> 4 float4/thread, B tile 32x128 -> 4.
    float4 aSt[4], bSt[4];

    // ---- load first tile into registers ----
    #pragma unroll
    for (int i = 0; i < 4; i++) {
        int s = tid + i * 256;
        int r = s >> 3, c4 = s & 7;           // A: row 0..127, col4 0..7
        int ga = brow + r;
        aSt[i] = (ga < M)
            ? *reinterpret_cast<const float4*>(A + (size_t)ga * K + c4 * 4)
            : make_float4(0.f, 0.f, 0.f, 0.f);
        int rb = s >> 5, cb = s & 31;         // B: row 0..31, col4 0..31
        bSt[i] = *reinterpret_cast<const float4*>(Bm + (size_t)rb * N + bcol + cb * 4);
    }
    // store (with tf32 rounding) into smem
    #pragma unroll
    for (int i = 0; i < 4; i++) {
        int s = tid + i * 256;
        int r = s >> 3, c4 = s & 7;
        As[r][c4 * 4 + 0] = to_tf32(aSt[i].x);
        As[r][c4 * 4 + 1] = to_tf32(aSt[i].y);
        As[r][c4 * 4 + 2] = to_tf32(aSt[i].z);
        As[r][c4 * 4 + 3] = to_tf32(aSt[i].w);
        int rb = s >> 5, cb = s & 31;
        Bs[rb][cb * 4 + 0] = to_tf32(bSt[i].x);
        Bs[rb][cb * 4 + 1] = to_tf32(bSt[i].y);
        Bs[rb][cb * 4 + 2] = to_tf32(bSt[i].z);
        Bs[rb][cb * 4 + 3] = to_tf32(bSt[i].w);
    }

    for (int k0 = 0; k0 < K; k0 += 32) {
        __syncthreads();

        bool more = (k0 + 32 < K);
        if (more) {
            #pragma unroll
            for (int i = 0; i < 4; i++) {
                int s = tid + i * 256;
                int r = s >> 3, c4 = s & 7;
                int ga = brow + r;
                aSt[i] = (ga < M)
                    ? *reinterpret_cast<const float4*>(A + (size_t)ga * K + k0 + 32 + c4 * 4)
                    : make_float4(0.f, 0.f, 0.f, 0.f);
                int rb = s >> 5, cb = s & 31;
                bSt[i] = *reinterpret_cast<const float4*>(
                    Bm + (size_t)(k0 + 32 + rb) * N + bcol + cb * 4);
            }
        }

        // ---- compute 4 k-steps of 8 ----
        #pragma unroll
        for (int ks = 0; ks < 32; ks += 8) {
            uint32_t af[4][4], bf[4][2];
            #pragma unroll
            for (int mi = 0; mi < 4; mi++) {
                int r = mBase + mi * 16;
                af[mi][0] = __float_as_uint(As[r + qr    ][ks + qc    ]);
                af[mi][1] = __float_as_uint(As[r + qr + 8][ks + qc    ]);
                af[mi][2] = __float_as_uint(As[r + qr    ][ks + qc + 4]);
                af[mi][3] = __float_as_uint(As[r + qr + 8][ks + qc + 4]);
            }
            #pragma unroll
            for (int nj = 0; nj < 4; nj++) {
                int c = nBase + nj * 8 + qr;
                bf[nj][0] = __float_as_uint(Bs[ks + qc    ][c]);
                bf[nj][1] = __float_as_uint(Bs[ks + qc + 4][c]);
            }
            #pragma unroll
            for (int mi = 0; mi < 4; mi++)
                #pragma unroll
                for (int nj = 0; nj < 4; nj++)
                    mma_tf32(acc[mi][nj], af[mi], bf[nj]);
        }

        __syncthreads();

        if (more) {
            #pragma unroll
            for (int i = 0; i < 4; i++) {
                int s = tid + i * 256;
                int r = s >> 3, c4 = s & 7;
                As[r][c4 * 4 + 0] = to_tf32(aSt[i].x);
                As[r][c4 * 4 + 1] = to_tf32(aSt[i].y);
                As[r][c4 * 4 + 2] = to_tf32(aSt[i].z);
                As[r][c4 * 4 + 3] = to_tf32(aSt[i].w);
                int rb = s >> 5, cb = s & 31;
                Bs[rb][cb * 4 + 0] = to_tf32(bSt[i].x);
                Bs[rb][cb * 4 + 1] = to_tf32(bSt[i].y);
                Bs[rb][cb * 4 + 2] = to_tf32(bSt[i].z);
                Bs[rb][cb * 4 + 3] = to_tf32(bSt[i].w);
            }
        }
    }

    // ---- epilogue: (acc + bias) * scale ----
    #pragma unroll
    for (int mi = 0; mi < 4; mi++) {
        int row0 = brow + mBase + mi * 16 + qr;
        #pragma unroll
        for (int nj = 0; nj < 4; nj++) {
            int col0 = bcol + nBase + nj * 8 + qc * 2;
            float b0 = bias[col0], b1 = bias[col0 + 1];
            if (row0 < M) {
                C[(size_t)row0 * N + col0    ] = (acc[mi][nj][0] + b0) * scale;
                C[(size_t)row0 * N + col0 + 1] = (acc[mi][nj][1] + b1) * scale;
            }
            if (row0 + 8 < M) {
                C[(size_t)(row0 + 8) * N + col0    ] = (acc[mi][nj][2] + b0) * scale;
                C[(size_t)(row0 + 8) * N + col0 + 1] = (acc[mi][nj][3] + b1) * scale;
            }
        }
    }
}

// ---------------------------------------------------------------------------
// Flash-style cross attention (unchanged from R2 baseline).
// ---------------------------------------------------------------------------
__global__ __launch_bounds__(256) void attn_kernel(
    const float* __restrict__ q, const float* __restrict__ kv,
    const int* __restrict__ seq_lens, float* __restrict__ outbuf,
    int nB, int enc)
{
    __shared__ float Qs[TQ][HDIM + 4];
    __shared__ float Ks[TK][HDIM + 4];
    __shared__ float Vs[TK][HDIM + 4];
    __shared__ float Ps[TQ][TK + 4];

    int h = blockIdx.x;
    int b = blockIdx.y;
    int tile = blockIdx.z;

    int qstart = 0;
    for (int i = 0; i < b; i++) qstart += seq_lens[i];
    int qlen = seq_lens[b];
    if (tile * TQ >= qlen) return;
    int qrow0 = qstart + tile * TQ;
    int rows = min(TQ, qlen - tile * TQ);
    size_t kvbase = (size_t)b * enc;

    int tid = threadIdx.x;
    for (int i = tid; i < TQ * HDIM; i += 256) {
        int r = i >> 6, c = i & 63;
        Qs[r][c] = (r < rows) ? q[(size_t)(qrow0 + r) * D + h * HDIM + c] : 0.f;
    }

    int tx = tid & 15, ty = tid >> 4;
    int r0 = ty * 4, c0 = tx * 2, hc = tx * 4;

    float m[4], l[4], O[4][4];
    #pragma unroll
    for (int i = 0; i < 4; i++) {
        m[i] = -1e30f; l[i] = 0.f;
        #pragma unroll
        for (int j = 0; j < 4; j++) O[i][j] = 0.f;
    }
    __syncthreads();

    for (int kc = 0; kc < enc; kc += TK) {
        int kn = min(TK, enc - kc);
        for (int i = tid; i < TK * HDIM; i += 256) {
            int r = i >> 6, c = i & 63;
            float kval = 0.f, vval = 0.f;
            if (r < kn) {
                const float* rowp = kv + (kvbase + kc + r) * (size_t)(2 * D) + h * HDIM;
                kval = rowp[c];
                vval = rowp[D + c];
            }
            Ks[r][c] = kval;
            Vs[r][c] = vval;
        }
        __syncthreads();

        float S[4][2];
        #pragma unroll
        for (int i = 0; i < 4; i++) { S[i][0] = 0.f; S[i][1] = 0.f; }
        #pragma unroll 4
        for (int d = 0; d < HDIM; d++) {
            float k0v = Ks[c0][d], k1v = Ks[c0 + 1][d];
            #pragma unroll
            for (int i = 0; i < 4; i++) {
                float qv = Qs[r0 + i][d];
                S[i][0] += qv * k0v;
                S[i][1] += qv * k1v;
            }
        }
        bool v0 = (c0 < kn), v1 = (c0 + 1 < kn);
        #pragma unroll
        for (int i = 0; i < 4; i++) {
            if (!v0) S[i][0] = -1e30f;
            if (!v1) S[i][1] = -1e30f;
        }

        #pragma unroll
        for (int i = 0; i < 4; i++) {
            float mc = fmaxf(S[i][0], S[i][1]);
            #pragma unroll
            for (int off = 1; off < 16; off <<= 1)
                mc = fmaxf(mc, __shfl_xor_sync(0xffffffffu, mc, off));
            float mn = fmaxf(m[i], mc);
            float alpha = __expf(m[i] - mn);
            m[i] = mn;
            float p0 = __expf(S[i][0] - mn);
            float p1 = __expf(S[i][1] - mn);
            Ps[r0 + i][c0] = p0;
            Ps[r0 + i][c0 + 1] = p1;
            float rs = p0 + p1;
            #pragma unroll
            for (int off = 1; off < 16; off <<= 1)
                rs += __shfl_xor_sync(0xffffffffu, rs, off);
            l[i] = l[i] * alpha + rs;
            #pragma unroll
            for (int j = 0; j < 4; j++) O[i][j] *= alpha;
        }
        __syncthreads();

        #pragma unroll 4
        for (int kk = 0; kk < TK; kk++) {
            float vv0 = Vs[kk][hc], vv1 = Vs[kk][hc + 1];
            float vv2 = Vs[kk][hc + 2], vv3 = Vs[kk][hc + 3];
            #pragma unroll
            for (int i = 0; i < 4; i++) {
                float p = Ps[r0 + i][kk];
                O[i][0] += p * vv0;
                O[i][1] += p * vv1;
                O[i][2] += p * vv2;
                O[i][3] += p * vv3;
            }
        }
        __syncthreads();
    }

    #pragma unroll
    for (int i = 0; i < 4; i++) {
        if (r0 + i < rows) {
            float inv = 1.f / l[i];
            #pragma unroll
            for (int j = 0; j < 4; j++)
                outbuf[(size_t)(qrow0 + r0 + i) * D + h * HDIM + hc + j] = O[i][j] * inv;
        }
    }
}

// ---------------------------------------------------------------------------
// kernel_launch: Qproj -> KVproj -> flash attention -> Oproj
// ---------------------------------------------------------------------------
extern "C" void kernel_launch(void* const* d_in, const int* in_sizes, int n_in,
                              void* d_out, int out_size)
{
    const float* hidden = (const float*)d_in[0];
    const float* cross  = (const float*)d_in[1];
    const int*   seqs   = (const int*)d_in[2];
    const float* Wq  = (const float*)d_in[3];
    const float* bq  = (const float*)d_in[4];
    const float* Wkv = (const float*)d_in[5];
    const float* bkv = (const float*)d_in[6];
    const float* Wo  = (const float*)d_in[7];
    const float* bo  = (const float*)d_in[8];
    float* out = (float*)d_out;

    int qlen  = in_sizes[0] / D;
    int kvlen = in_sizes[1] / D;
    int nB    = in_sizes[2];
    int enc   = kvlen / nB;

    float *qbuf, *kvbuf, *abuf;
    cudaGetSymbolAddress((void**)&qbuf, g_q);
    cudaGetSymbolAddress((void**)&kvbuf, g_kv);
    cudaGetSymbolAddress((void**)&abuf, g_attn);

    dim3 blk(256);
    float scaling = 1.0f / sqrtf((float)HDIM);

    // Q projection (scaling fused)
    gemm_tf32_kernel<<<dim3(D / 128, (qlen + 127) / 128), blk>>>(
        hidden, Wq, bq, qbuf, qlen, D, D, scaling);

    // KV projection
    gemm_tf32_kernel<<<dim3((2 * D) / 128, (kvlen + 127) / 128), blk>>>(
        cross, Wkv, bkv, kvbuf, kvlen, 2 * D, D, 1.0f);

    // Fused attention
    int qtiles = (qlen + TQ - 1) / TQ;
    attn_kernel<<<dim3(H, nB, qtiles), blk>>>(qbuf, kvbuf, seqs, abuf, nB, enc);

    // Output projection
    gemm_tf32_kernel<<<dim3(D / 128, (qlen + 127) / 128), blk>>>(
        abuf, Wo, bo, out, qlen, D, D, 1.0f);
}

// round 5
// speedup vs baseline: 3.4714x; 1.9081x over previous
#include <cuda_runtime.h>
#include <math.h>
#include <stdint.h>

#define D    1280
#define H    20
#define HDIM 64

// Attention tiling
#define AT_TQ 128
#define AT_TK 64
#define QS_STRIDE 68
#define KS_STRIDE 68
#define VS_STRIDE 72
#define PS_STRIDE 68
#define ATTN_SMEM_FLOATS (AT_TQ*QS_STRIDE + AT_TK*KS_STRIDE + AT_TK*VS_STRIDE + AT_TQ*PS_STRIDE)
#define ATTN_SMEM_BYTES (ATTN_SMEM_FLOATS * 4)

// Scratch (allocation-free): sized for the fixed problem shapes.
__device__ float g_q[1600 * 1280];
__device__ float g_kv[6000 * 2560];
__device__ float g_attn[1600 * 1280];

// ---------------------------------------------------------------------------
// tf32 helpers
// ---------------------------------------------------------------------------
__device__ __forceinline__ float to_tf32(float x) {
    uint32_t y;
    asm("cvt.rna.tf32.f32 %0, %1;" : "=r"(y) : "f"(x));
    return __uint_as_float(y);
}

__device__ __forceinline__ void mma_tf32(float* d, const uint32_t* a, const uint32_t* b) {
    asm volatile(
        "mma.sync.aligned.m16n8k8.row.col.f32.tf32.tf32.f32 "
        "{%0,%1,%2,%3}, {%4,%5,%6,%7}, {%8,%9}, {%0,%1,%2,%3};\n"
        : "+f"(d[0]), "+f"(d[1]), "+f"(d[2]), "+f"(d[3])
        : "r"(a[0]), "r"(a[1]), "r"(a[2]), "r"(a[3]), "r"(b[0]), "r"(b[1]));
}

// ---------------------------------------------------------------------------
// TF32 tensor-core GEMM: C[M,N] = (A[M,K] @ B[K,N] + bias[N]) * scale
// BM=BN=128, BK=32. 256 threads = 8 warps in a 2(M) x 4(N) grid.
// ---------------------------------------------------------------------------
__global__ __launch_bounds__(256) void gemm_tf32_kernel(
    const float* __restrict__ A, const float* __restrict__ Bm,
    const float* __restrict__ bias, float* __restrict__ C,
    int M, int N, int K, float scale)
{
    __shared__ float As[128][36];   // [m][k]
    __shared__ float Bs[32][136];   // [k][n]

    int tid  = threadIdx.x;
    int wid  = tid >> 5, lane = tid & 31;
    int wm   = wid >> 2, wn = wid & 3;
    int qr   = lane >> 2, qc = lane & 3;
    int brow = blockIdx.y * 128;
    int bcol = blockIdx.x * 128;

    int mBase = wm * 64, nBase = wn * 32;

    float acc[4][4][4];
    #pragma unroll
    for (int i = 0; i < 4; i++)
        #pragma unroll
        for (int j = 0; j < 4; j++)
            #pragma unroll
            for (int t = 0; t < 4; t++) acc[i][j][t] = 0.f;

    float4 aSt[4], bSt[4];

    #pragma unroll
    for (int i = 0; i < 4; i++) {
        int s = tid + i * 256;
        int r = s >> 3, c4 = s & 7;
        int ga = brow + r;
        aSt[i] = (ga < M)
            ? *reinterpret_cast<const float4*>(A + (size_t)ga * K + c4 * 4)
            : make_float4(0.f, 0.f, 0.f, 0.f);
        int rb = s >> 5, cb = s & 31;
        bSt[i] = *reinterpret_cast<const float4*>(Bm + (size_t)rb * N + bcol + cb * 4);
    }
    #pragma unroll
    for (int i = 0; i < 4; i++) {
        int s = tid + i * 256;
        int r = s >> 3, c4 = s & 7;
        As[r][c4 * 4 + 0] = to_tf32(aSt[i].x);
        As[r][c4 * 4 + 1] = to_tf32(aSt[i].y);
        As[r][c4 * 4 + 2] = to_tf32(aSt[i].z);
        As[r][c4 * 4 + 3] = to_tf32(aSt[i].w);
        int rb = s >> 5, cb = s & 31;
        Bs[rb][cb * 4 + 0] = to_tf32(bSt[i].x);
        Bs[rb][cb * 4 + 1] = to_tf32(bSt[i].y);
        Bs[rb][cb * 4 + 2] = to_tf32(bSt[i].z);
        Bs[rb][cb * 4 + 3] = to_tf32(bSt[i].w);
    }

    for (int k0 = 0; k0 < K; k0 += 32) {
        __syncthreads();

        bool more = (k0 + 32 < K);
        if (more) {
            #pragma unroll
            for (int i = 0; i < 4; i++) {
                int s = tid + i * 256;
                int r = s >> 3, c4 = s & 7;
                int ga = brow + r;
                aSt[i] = (ga < M)
                    ? *reinterpret_cast<const float4*>(A + (size_t)ga * K + k0 + 32 + c4 * 4)
                    : make_float4(0.f, 0.f, 0.f, 0.f);
                int rb = s >> 5, cb = s & 31;
                bSt[i] = *reinterpret_cast<const float4*>(
                    Bm + (size_t)(k0 + 32 + rb) * N + bcol + cb * 4);
            }
        }

        #pragma unroll
        for (int ks = 0; ks < 32; ks += 8) {
            uint32_t af[4][4], bf[4][2];
            #pragma unroll
            for (int mi = 0; mi < 4; mi++) {
                int r = mBase + mi * 16;
                af[mi][0] = __float_as_uint(As[r + qr    ][ks + qc    ]);
                af[mi][1] = __float_as_uint(As[r + qr + 8][ks + qc    ]);
                af[mi][2] = __float_as_uint(As[r + qr    ][ks + qc + 4]);
                af[mi][3] = __float_as_uint(As[r + qr + 8][ks + qc + 4]);
            }
            #pragma unroll
            for (int nj = 0; nj < 4; nj++) {
                int c = nBase + nj * 8 + qr;
                bf[nj][0] = __float_as_uint(Bs[ks + qc    ][c]);
                bf[nj][1] = __float_as_uint(Bs[ks + qc + 4][c]);
            }
            #pragma unroll
            for (int mi = 0; mi < 4; mi++)
                #pragma unroll
                for (int nj = 0; nj < 4; nj++)
                    mma_tf32(acc[mi][nj], af[mi], bf[nj]);
        }

        __syncthreads();

        if (more) {
            #pragma unroll
            for (int i = 0; i < 4; i++) {
                int s = tid + i * 256;
                int r = s >> 3, c4 = s & 7;
                As[r][c4 * 4 + 0] = to_tf32(aSt[i].x);
                As[r][c4 * 4 + 1] = to_tf32(aSt[i].y);
                As[r][c4 * 4 + 2] = to_tf32(aSt[i].z);
                As[r][c4 * 4 + 3] = to_tf32(aSt[i].w);
                int rb = s >> 5, cb = s & 31;
                Bs[rb][cb * 4 + 0] = to_tf32(bSt[i].x);
                Bs[rb][cb * 4 + 1] = to_tf32(bSt[i].y);
                Bs[rb][cb * 4 + 2] = to_tf32(bSt[i].z);
                Bs[rb][cb * 4 + 3] = to_tf32(bSt[i].w);
            }
        }
    }

    #pragma unroll
    for (int mi = 0; mi < 4; mi++) {
        int row0 = brow + mBase + mi * 16 + qr;
        #pragma unroll
        for (int nj = 0; nj < 4; nj++) {
            int col0 = bcol + nBase + nj * 8 + qc * 2;
            float b0 = bias[col0], b1 = bias[col0 + 1];
            if (row0 < M) {
                C[(size_t)row0 * N + col0    ] = (acc[mi][nj][0] + b0) * scale;
                C[(size_t)row0 * N + col0 + 1] = (acc[mi][nj][1] + b1) * scale;
            }
            if (row0 + 8 < M) {
                C[(size_t)(row0 + 8) * N + col0    ] = (acc[mi][nj][2] + b0) * scale;
                C[(size_t)(row0 + 8) * N + col0 + 1] = (acc[mi][nj][3] + b1) * scale;
            }
        }
    }
}

// ---------------------------------------------------------------------------
// Tensor-core flash attention.
// Block = (head, batch, q-tile of 128). 8 warps; warp w owns query rows
// [16w, 16w+16) x all 64 key columns. Online softmax entirely in-quad.
// ---------------------------------------------------------------------------
__global__ __launch_bounds__(256) void attn_mma_kernel(
    const float* __restrict__ q, const float* __restrict__ kv,
    const int* __restrict__ seq_lens, float* __restrict__ outbuf,
    int nB, int enc)
{
    extern __shared__ float sm[];
    float* Qs = sm;                               // [AT_TQ][QS_STRIDE]
    float* Ks = Qs + AT_TQ * QS_STRIDE;           // [AT_TK][KS_STRIDE]
    float* Vs = Ks + AT_TK * KS_STRIDE;           // [AT_TK][VS_STRIDE]
    float* Ps = Vs + AT_TK * VS_STRIDE;           // [AT_TQ][PS_STRIDE]

    int h = blockIdx.x, b = blockIdx.y, tile = blockIdx.z;
    int qstart = 0;
    for (int i = 0; i < b; i++) qstart += seq_lens[i];
    int qlen = seq_lens[b];
    if (tile * AT_TQ >= qlen) return;
    int qrow0 = qstart + tile * AT_TQ;
    int rows = min(AT_TQ, qlen - tile * AT_TQ);
    size_t kvbase = (size_t)b * enc;

    int tid = threadIdx.x, wid = tid >> 5, lane = tid & 31;
    int qr = lane >> 2, qc = lane & 3;
    int mrow = wid * 16;

    // ---- load Q tile (convert tf32) ----
    for (int i = tid; i < AT_TQ * 16; i += 256) {
        int r = i >> 4, c4 = (i & 15) << 2;
        float4 v = make_float4(0.f, 0.f, 0.f, 0.f);
        if (r < rows)
            v = *reinterpret_cast<const float4*>(q + (size_t)(qrow0 + r) * D + h * HDIM + c4);
        float* p = Qs + r * QS_STRIDE + c4;
        p[0] = to_tf32(v.x); p[1] = to_tf32(v.y);
        p[2] = to_tf32(v.z); p[3] = to_tf32(v.w);
    }

    float O[8][4];
    #pragma unroll
    for (int nj = 0; nj < 8; nj++)
        #pragma unroll
        for (int t = 0; t < 4; t++) O[nj][t] = 0.f;
    float m0 = -1e30f, m1 = -1e30f, l0 = 0.f, l1 = 0.f;

    __syncthreads();

    for (int kc = 0; kc < enc; kc += AT_TK) {
        int kn = min(AT_TK, enc - kc);

        // ---- load K/V chunk (convert tf32) ----
        for (int i = tid; i < AT_TK * 16; i += 256) {
            int r = i >> 4, c4 = (i & 15) << 2;
            float4 kv4 = make_float4(0.f, 0.f, 0.f, 0.f);
            float4 vv4 = make_float4(0.f, 0.f, 0.f, 0.f);
            if (r < kn) {
                const float* rp = kv + (kvbase + kc + r) * (size_t)(2 * D) + h * HDIM;
                kv4 = *reinterpret_cast<const float4*>(rp + c4);
                vv4 = *reinterpret_cast<const float4*>(rp + D + c4);
            }
            float* pk = Ks + r * KS_STRIDE + c4;
            pk[0] = to_tf32(kv4.x); pk[1] = to_tf32(kv4.y);
            pk[2] = to_tf32(kv4.z); pk[3] = to_tf32(kv4.w);
            float* pv = Vs + r * VS_STRIDE + c4;
            pv[0] = to_tf32(vv4.x); pv[1] = to_tf32(vv4.y);
            pv[2] = to_tf32(vv4.z); pv[3] = to_tf32(vv4.w);
        }
        __syncthreads();

        // ---- S = Q @ K^T ----
        float s[8][4];
        #pragma unroll
        for (int nj = 0; nj < 8; nj++)
            #pragma unroll
            for (int t = 0; t < 4; t++) s[nj][t] = 0.f;

        #pragma unroll
        for (int ks = 0; ks < AT_TK; ks += 8) {
            uint32_t a[4];
            a[0] = __float_as_uint(Qs[(mrow + qr    ) * QS_STRIDE + ks + qc    ]);
            a[1] = __float_as_uint(Qs[(mrow + qr + 8) * QS_STRIDE + ks + qc    ]);
            a[2] = __float_as_uint(Qs[(mrow + qr    ) * QS_STRIDE + ks + qc + 4]);
            a[3] = __float_as_uint(Qs[(mrow + qr + 8) * QS_STRIDE + ks + qc + 4]);
            #pragma unroll
            for (int nj = 0; nj < 8; nj++) {
                uint32_t bb[2];
                bb[0] = __float_as_uint(Ks[(nj * 8 + qr) * KS_STRIDE + ks + qc    ]);
                bb[1] = __float_as_uint(Ks[(nj * 8 + qr) * KS_STRIDE + ks + qc + 4]);
                mma_tf32(s[nj], a, bb);
            }
        }

        // ---- mask tail keys ----
        if (kn < AT_TK) {
            #pragma unroll
            for (int nj = 0; nj < 8; nj++) {
                int c0 = nj * 8 + 2 * qc;
                if (c0     >= kn) { s[nj][0] = -1e30f; s[nj][2] = -1e30f; }
                if (c0 + 1 >= kn) { s[nj][1] = -1e30f; s[nj][3] = -1e30f; }
            }
        }

        // ---- online softmax (rows qr and qr+8, reduce over quad lanes) ----
        float mx0 = -1e30f, mx1 = -1e30f;
        #pragma unroll
        for (int nj = 0; nj < 8; nj++) {
            mx0 = fmaxf(mx0, fmaxf(s[nj][0], s[nj][1]));
            mx1 = fmaxf(mx1, fmaxf(s[nj][2], s[nj][3]));
        }
        mx0 = fmaxf(mx0, __shfl_xor_sync(0xffffffffu, mx0, 1));
        mx0 = fmaxf(mx0, __shfl_xor_sync(0xffffffffu, mx0, 2));
        mx1 = fmaxf(mx1, __shfl_xor_sync(0xffffffffu, mx1, 1));
        mx1 = fmaxf(mx1, __shfl_xor_sync(0xffffffffu, mx1, 2));

        float mn0 = fmaxf(m0, mx0), mn1 = fmaxf(m1, mx1);
        float al0 = __expf(m0 - mn0), al1 = __expf(m1 - mn1);
        m0 = mn0; m1 = mn1;

        float rs0 = 0.f, rs1 = 0.f;
        #pragma unroll
        for (int nj = 0; nj < 8; nj++) {
            float p0 = __expf(s[nj][0] - mn0);
            float p1 = __expf(s[nj][1] - mn0);
            float p2 = __expf(s[nj][2] - mn1);
            float p3 = __expf(s[nj][3] - mn1);
            rs0 += p0 + p1; rs1 += p2 + p3;
            int c = nj * 8 + 2 * qc;
            Ps[(mrow + qr    ) * PS_STRIDE + c    ] = to_tf32(p0);
            Ps[(mrow + qr    ) * PS_STRIDE + c + 1] = to_tf32(p1);
            Ps[(mrow + qr + 8) * PS_STRIDE + c    ] = to_tf32(p2);
            Ps[(mrow + qr + 8) * PS_STRIDE + c + 1] = to_tf32(p3);
            O[nj][0] *= al0; O[nj][1] *= al0;
            O[nj][2] *= al1; O[nj][3] *= al1;
        }
        rs0 += __shfl_xor_sync(0xffffffffu, rs0, 1);
        rs0 += __shfl_xor_sync(0xffffffffu, rs0, 2);
        rs1 += __shfl_xor_sync(0xffffffffu, rs1, 1);
        rs1 += __shfl_xor_sync(0xffffffffu, rs1, 2);
        l0 = l0 * al0 + rs0;
        l1 = l1 * al1 + rs1;

        __syncwarp();   // P rows are warp-private: warp-level visibility suffices

        // ---- O += P @ V ----
        #pragma unroll
        for (int ks = 0; ks < AT_TK; ks += 8) {
            uint32_t a[4];
            a[0] = __float_as_uint(Ps[(mrow + qr    ) * PS_STRIDE + ks + qc    ]);
            a[1] = __float_as_uint(Ps[(mrow + qr + 8) * PS_STRIDE + ks + qc    ]);
            a[2] = __float_as_uint(Ps[(mrow + qr    ) * PS_STRIDE + ks + qc + 4]);
            a[3] = __float_as_uint(Ps[(mrow + qr + 8) * PS_STRIDE + ks + qc + 4]);
            #pragma unroll
            for (int nj = 0; nj < 8; nj++) {
                uint32_t bb[2];
                bb[0] = __float_as_uint(Vs[(ks + qc    ) * VS_STRIDE + nj * 8 + qr]);
                bb[1] = __float_as_uint(Vs[(ks + qc + 4) * VS_STRIDE + nj * 8 + qr]);
                mma_tf32(O[nj], a, bb);
            }
        }
        __syncthreads();   // protect K/V/P before next chunk overwrites
    }

    // ---- write out O / l ----
    float inv0 = 1.f / l0, inv1 = 1.f / l1;
    int r0 = mrow + qr, r1 = mrow + qr + 8;
    #pragma unroll
    for (int nj = 0; nj < 8; nj++) {
        int c = h * HDIM + nj * 8 + 2 * qc;
        if (r0 < rows) {
            float* p = outbuf + (size_t)(qrow0 + r0) * D + c;
            p[0] = O[nj][0] * inv0;
            p[1] = O[nj][1] * inv0;
        }
        if (r1 < rows) {
            float* p = outbuf + (size_t)(qrow0 + r1) * D + c;
            p[0] = O[nj][2] * inv1;
            p[1] = O[nj][3] * inv1;
        }
    }
}

// ---------------------------------------------------------------------------
// kernel_launch: Qproj -> KVproj -> flash attention (MMA) -> Oproj
// ---------------------------------------------------------------------------
extern "C" void kernel_launch(void* const* d_in, const int* in_sizes, int n_in,
                              void* d_out, int out_size)
{
    const float* hidden = (const float*)d_in[0];
    const float* cross  = (const float*)d_in[1];
    const int*   seqs   = (const int*)d_in[2];
    const float* Wq  = (const float*)d_in[3];
    const float* bq  = (const float*)d_in[4];
    const float* Wkv = (const float*)d_in[5];
    const float* bkv = (const float*)d_in[6];
    const float* Wo  = (const float*)d_in[7];
    const float* bo  = (const float*)d_in[8];
    float* out = (float*)d_out;

    int qlen  = in_sizes[0] / D;
    int kvlen = in_sizes[1] / D;
    int nB    = in_sizes[2];
    int enc   = kvlen / nB;

    float *qbuf, *kvbuf, *abuf;
    cudaGetSymbolAddress((void**)&qbuf, g_q);
    cudaGetSymbolAddress((void**)&kvbuf, g_kv);
    cudaGetSymbolAddress((void**)&abuf, g_attn);

    cudaFuncSetAttribute(attn_mma_kernel,
                         cudaFuncAttributeMaxDynamicSharedMemorySize, ATTN_SMEM_BYTES);

    dim3 blk(256);
    float scaling = 1.0f / sqrtf((float)HDIM);

    // Q projection (scaling fused)
    gemm_tf32_kernel<<<dim3(D / 128, (qlen + 127) / 128), blk>>>(
        hidden, Wq, bq, qbuf, qlen, D, D, scaling);

    // KV projection
    gemm_tf32_kernel<<<dim3((2 * D) / 128, (kvlen + 127) / 128), blk>>>(
        cross, Wkv, bkv, kvbuf, kvlen, 2 * D, D, 1.0f);

    // Fused attention (tensor-core)
    int qtiles = (qlen + AT_TQ - 1) / AT_TQ;
    attn_mma_kernel<<<dim3(H, nB, qtiles), blk, ATTN_SMEM_BYTES>>>(
        qbuf, kvbuf, seqs, abuf, nB, enc);

    // Output projection
    gemm_tf32_kernel<<<dim3(D / 128, (qlen + 127) / 128), blk>>>(
        abuf, Wo, bo, out, qlen, D, D, 1.0f);
}

// round 6
// speedup vs baseline: 4.1496x; 1.1954x over previous
#include <cuda_runtime.h>
#include <math.h>
#include <stdint.h>

#define D    1280
#define H    20
#define HDIM 64

// Attention tiling
#define AT_TQ 128
#define AT_TK 64
#define QS_STRIDE 68
#define KS_STRIDE 68
#define VS_STRIDE 72
#define PS_STRIDE 68
#define ATTN_SMEM_FLOATS (AT_TQ*QS_STRIDE + AT_TK*KS_STRIDE + AT_TK*VS_STRIDE + AT_TQ*PS_STRIDE)
#define ATTN_SMEM_BYTES (ATTN_SMEM_FLOATS * 4)

// GEMM smem staging (2-stage cp.async pipeline)
#define GA_STRIDE 36
#define GB_STRIDE 136
#define GA_FLOATS (128 * GA_STRIDE)           // 4608
#define GB_FLOATS (32 * GB_STRIDE)            // 4352
#define GSTAGE_FLOATS (GA_FLOATS + GB_FLOATS) // 8960
#define GEMM_SMEM_BYTES (2 * GSTAGE_FLOATS * 4)  // 71680

// Scratch (allocation-free): fixed problem shapes.
__device__ float g_q[1600 * 1280];
__device__ float g_kv[6000 * 2560];
__device__ float g_attn[1600 * 1280];
__device__ float g_hid[1600 * 1280];
__device__ float g_cross[6000 * 1280];
__device__ float g_wq[1280 * 1280];
__device__ float g_wkv[1280 * 2560];
__device__ float g_wo[1280 * 1280];

// ---------------------------------------------------------------------------
// tf32 / cp.async helpers
// ---------------------------------------------------------------------------
__device__ __forceinline__ float to_tf32(float x) {
    uint32_t y;
    asm("cvt.rna.tf32.f32 %0, %1;" : "=r"(y) : "f"(x));
    return __uint_as_float(y);
}

__device__ __forceinline__ void mma_tf32(float* d, const uint32_t* a, const uint32_t* b) {
    asm volatile(
        "mma.sync.aligned.m16n8k8.row.col.f32.tf32.tf32.f32 "
        "{%0,%1,%2,%3}, {%4,%5,%6,%7}, {%8,%9}, {%0,%1,%2,%3};\n"
        : "+f"(d[0]), "+f"(d[1]), "+f"(d[2]), "+f"(d[3])
        : "r"(a[0]), "r"(a[1]), "r"(a[2]), "r"(a[3]), "r"(b[0]), "r"(b[1]));
}

__device__ __forceinline__ uint32_t smem_u32(const void* p) {
    return (uint32_t)__cvta_generic_to_shared(p);
}

__device__ __forceinline__ void cp16(uint32_t dst, const void* src, bool pred) {
    int sz = pred ? 16 : 0;
    asm volatile("cp.async.ca.shared.global [%0], [%1], 16, %2;\n"
                 :: "r"(dst), "l"(src), "r"(sz));
}
#define CP_COMMIT() asm volatile("cp.async.commit_group;\n" ::: "memory")
#define CP_WAIT1()  asm volatile("cp.async.wait_group 1;\n" ::: "memory")
#define CP_WAIT0()  asm volatile("cp.async.wait_group 0;\n" ::: "memory")

// ---------------------------------------------------------------------------
// Elementwise fp32 -> tf32(RN) conversion (vectorized).
// ---------------------------------------------------------------------------
__global__ void cvt_tf32_kernel(const float* __restrict__ in,
                                float* __restrict__ out, int n4)
{
    int i = blockIdx.x * blockDim.x + threadIdx.x;
    if (i < n4) {
        float4 v = reinterpret_cast<const float4*>(in)[i];
        v.x = to_tf32(v.x); v.y = to_tf32(v.y);
        v.z = to_tf32(v.z); v.w = to_tf32(v.w);
        reinterpret_cast<float4*>(out)[i] = v;
    }
}

// ---------------------------------------------------------------------------
// TF32 GEMM with cp.async double buffering. Inputs must be pre-rounded tf32.
// C[M,N] = (A@B + bias) * scale, optionally tf32-rounded on output.
// BM=BN=128, BK=32. 256 threads = 8 warps (2M x 4N), warp tile 64x32.
// ---------------------------------------------------------------------------
__global__ __launch_bounds__(256, 2) void gemm_tf32_cp_kernel(
    const float* __restrict__ A, const float* __restrict__ Bm,
    const float* __restrict__ bias, float* __restrict__ C,
    int M, int N, int K, float scale, int round_out)
{
    extern __shared__ float sm[];

    int tid  = threadIdx.x;
    int wid  = tid >> 5, lane = tid & 31;
    int wm   = wid >> 2, wn = wid & 3;
    int qr   = lane >> 2, qc = lane & 3;
    int brow = blockIdx.y * 128;
    int bcol = blockIdx.x * 128;
    int mBase = wm * 64, nBase = wn * 32;

    float acc[4][4][4];
    #pragma unroll
    for (int i = 0; i < 4; i++)
        #pragma unroll
        for (int j = 0; j < 4; j++)
            #pragma unroll
            for (int t = 0; t < 4; t++) acc[i][j][t] = 0.f;

    int ntiles = K >> 5;

    // Precompute per-thread copy coordinates.
    // A: 4 chunks, s = tid + i*256 -> r = s>>3, c4 = (s&7)*4
    // B: 4 chunks, rb = s>>5, cb = (s&31)*4

    auto issue = [&](int tile, int buf) {
        float* As = sm + buf * GSTAGE_FLOATS;
        float* Bs = As + GA_FLOATS;
        int k0 = tile << 5;
        #pragma unroll
        for (int i = 0; i < 4; i++) {
            int s = tid + i * 256;
            int r = s >> 3, c4 = (s & 7) << 2;
            int ga = brow + r;
            bool p = (ga < M);
            const float* srcA = A + (size_t)(p ? ga : 0) * K + k0 + c4;
            cp16(smem_u32(As + r * GA_STRIDE + c4), srcA, p);
            int rb = s >> 5, cb = (s & 31) << 2;
            const float* srcB = Bm + (size_t)(k0 + rb) * N + bcol + cb;
            cp16(smem_u32(Bs + rb * GB_STRIDE + cb), srcB, true);
        }
        CP_COMMIT();
    };

    issue(0, 0);

    for (int t = 0; t < ntiles; t++) {
        int buf = t & 1;
        if (t + 1 < ntiles) {
            issue(t + 1, buf ^ 1);
            CP_WAIT1();
        } else {
            CP_WAIT0();
        }
        __syncthreads();

        float* As = sm + buf * GSTAGE_FLOATS;
        float* Bs = As + GA_FLOATS;

        #pragma unroll
        for (int ks = 0; ks < 32; ks += 8) {
            uint32_t af[4][4], bf[4][2];
            #pragma unroll
            for (int mi = 0; mi < 4; mi++) {
                int r = mBase + mi * 16;
                af[mi][0] = __float_as_uint(As[(r + qr    ) * GA_STRIDE + ks + qc    ]);
                af[mi][1] = __float_as_uint(As[(r + qr + 8) * GA_STRIDE + ks + qc    ]);
                af[mi][2] = __float_as_uint(As[(r + qr    ) * GA_STRIDE + ks + qc + 4]);
                af[mi][3] = __float_as_uint(As[(r + qr + 8) * GA_STRIDE + ks + qc + 4]);
            }
            #pragma unroll
            for (int nj = 0; nj < 4; nj++) {
                int c = nBase + nj * 8 + qr;
                bf[nj][0] = __float_as_uint(Bs[(ks + qc    ) * GB_STRIDE + c]);
                bf[nj][1] = __float_as_uint(Bs[(ks + qc + 4) * GB_STRIDE + c]);
            }
            #pragma unroll
            for (int mi = 0; mi < 4; mi++)
                #pragma unroll
                for (int nj = 0; nj < 4; nj++)
                    mma_tf32(acc[mi][nj], af[mi], bf[nj]);
        }
        __syncthreads();
    }

    // ---- epilogue ----
    #pragma unroll
    for (int mi = 0; mi < 4; mi++) {
        int row0 = brow + mBase + mi * 16 + qr;
        #pragma unroll
        for (int nj = 0; nj < 4; nj++) {
            int col0 = bcol + nBase + nj * 8 + qc * 2;
            float b0 = bias[col0], b1 = bias[col0 + 1];
            float v00 = (acc[mi][nj][0] + b0) * scale;
            float v01 = (acc[mi][nj][1] + b1) * scale;
            float v10 = (acc[mi][nj][2] + b0) * scale;
            float v11 = (acc[mi][nj][3] + b1) * scale;
            if (round_out) {
                v00 = to_tf32(v00); v01 = to_tf32(v01);
                v10 = to_tf32(v10); v11 = to_tf32(v11);
            }
            if (row0 < M) {
                C[(size_t)row0 * N + col0    ] = v00;
                C[(size_t)row0 * N + col0 + 1] = v01;
            }
            if (row0 + 8 < M) {
                C[(size_t)(row0 + 8) * N + col0    ] = v10;
                C[(size_t)(row0 + 8) * N + col0 + 1] = v11;
            }
        }
    }
}

// ---------------------------------------------------------------------------
// Tensor-core flash attention. Inputs (q, kv) pre-rounded tf32.
// Block = (head, batch, q-tile of 128). 8 warps; warp w owns 16 query rows.
// ---------------------------------------------------------------------------
__global__ __launch_bounds__(256) void attn_mma_kernel(
    const float* __restrict__ q, const float* __restrict__ kv,
    const int* __restrict__ seq_lens, float* __restrict__ outbuf,
    int nB, int enc)
{
    extern __shared__ float sm[];
    float* Qs = sm;
    float* Ks = Qs + AT_TQ * QS_STRIDE;
    float* Vs = Ks + AT_TK * KS_STRIDE;
    float* Ps = Vs + AT_TK * VS_STRIDE;

    int h = blockIdx.x, b = blockIdx.y, tile = blockIdx.z;
    int qstart = 0;
    for (int i = 0; i < b; i++) qstart += seq_lens[i];
    int qlen = seq_lens[b];
    if (tile * AT_TQ >= qlen) return;
    int qrow0 = qstart + tile * AT_TQ;
    int rows = min(AT_TQ, qlen - tile * AT_TQ);
    size_t kvbase = (size_t)b * enc;

    int tid = threadIdx.x, wid = tid >> 5, lane = tid & 31;
    int qr = lane >> 2, qc = lane & 3;
    int mrow = wid * 16;

    for (int i = tid; i < AT_TQ * 16; i += 256) {
        int r = i >> 4, c4 = (i & 15) << 2;
        float4 v = make_float4(0.f, 0.f, 0.f, 0.f);
        if (r < rows)
            v = *reinterpret_cast<const float4*>(q + (size_t)(qrow0 + r) * D + h * HDIM + c4);
        *reinterpret_cast<float4*>(Qs + r * QS_STRIDE + c4) = v;
    }

    float O[8][4];
    #pragma unroll
    for (int nj = 0; nj < 8; nj++)
        #pragma unroll
        for (int t = 0; t < 4; t++) O[nj][t] = 0.f;
    float m0 = -1e30f, m1 = -1e30f, l0 = 0.f, l1 = 0.f;

    __syncthreads();

    for (int kc = 0; kc < enc; kc += AT_TK) {
        int kn = min(AT_TK, enc - kc);

        for (int i = tid; i < AT_TK * 16; i += 256) {
            int r = i >> 4, c4 = (i & 15) << 2;
            float4 kv4 = make_float4(0.f, 0.f, 0.f, 0.f);
            float4 vv4 = make_float4(0.f, 0.f, 0.f, 0.f);
            if (r < kn) {
                const float* rp = kv + (kvbase + kc + r) * (size_t)(2 * D) + h * HDIM;
                kv4 = *reinterpret_cast<const float4*>(rp + c4);
                vv4 = *reinterpret_cast<const float4*>(rp + D + c4);
            }
            *reinterpret_cast<float4*>(Ks + r * KS_STRIDE + c4) = kv4;
            *reinterpret_cast<float4*>(Vs + r * VS_STRIDE + c4) = vv4;
        }
        __syncthreads();

        float s[8][4];
        #pragma unroll
        for (int nj = 0; nj < 8; nj++)
            #pragma unroll
            for (int t = 0; t < 4; t++) s[nj][t] = 0.f;

        #pragma unroll
        for (int ks = 0; ks < AT_TK; ks += 8) {
            uint32_t a[4];
            a[0] = __float_as_uint(Qs[(mrow + qr    ) * QS_STRIDE + ks + qc    ]);
            a[1] = __float_as_uint(Qs[(mrow + qr + 8) * QS_STRIDE + ks + qc    ]);
            a[2] = __float_as_uint(Qs[(mrow + qr    ) * QS_STRIDE + ks + qc + 4]);
            a[3] = __float_as_uint(Qs[(mrow + qr + 8) * QS_STRIDE + ks + qc + 4]);
            #pragma unroll
            for (int nj = 0; nj < 8; nj++) {
                uint32_t bb[2];
                bb[0] = __float_as_uint(Ks[(nj * 8 + qr) * KS_STRIDE + ks + qc    ]);
                bb[1] = __float_as_uint(Ks[(nj * 8 + qr) * KS_STRIDE + ks + qc + 4]);
                mma_tf32(s[nj], a, bb);
            }
        }

        if (kn < AT_TK) {
            #pragma unroll
            for (int nj = 0; nj < 8; nj++) {
                int c0 = nj * 8 + 2 * qc;
                if (c0     >= kn) { s[nj][0] = -1e30f; s[nj][2] = -1e30f; }
                if (c0 + 1 >= kn) { s[nj][1] = -1e30f; s[nj][3] = -1e30f; }
            }
        }

        float mx0 = -1e30f, mx1 = -1e30f;
        #pragma unroll
        for (int nj = 0; nj < 8; nj++) {
            mx0 = fmaxf(mx0, fmaxf(s[nj][0], s[nj][1]));
            mx1 = fmaxf(mx1, fmaxf(s[nj][2], s[nj][3]));
        }
        mx0 = fmaxf(mx0, __shfl_xor_sync(0xffffffffu, mx0, 1));
        mx0 = fmaxf(mx0, __shfl_xor_sync(0xffffffffu, mx0, 2));
        mx1 = fmaxf(mx1, __shfl_xor_sync(0xffffffffu, mx1, 1));
        mx1 = fmaxf(mx1, __shfl_xor_sync(0xffffffffu, mx1, 2));

        float mn0 = fmaxf(m0, mx0), mn1 = fmaxf(m1, mx1);
        float al0 = __expf(m0 - mn0), al1 = __expf(m1 - mn1);
        m0 = mn0; m1 = mn1;

        float rs0 = 0.f, rs1 = 0.f;
        #pragma unroll
        for (int nj = 0; nj < 8; nj++) {
            float p0 = __expf(s[nj][0] - mn0);
            float p1 = __expf(s[nj][1] - mn0);
            float p2 = __expf(s[nj][2] - mn1);
            float p3 = __expf(s[nj][3] - mn1);
            rs0 += p0 + p1; rs1 += p2 + p3;
            int c = nj * 8 + 2 * qc;
            Ps[(mrow + qr    ) * PS_STRIDE + c    ] = to_tf32(p0);
            Ps[(mrow + qr    ) * PS_STRIDE + c + 1] = to_tf32(p1);
            Ps[(mrow + qr + 8) * PS_STRIDE + c    ] = to_tf32(p2);
            Ps[(mrow + qr + 8) * PS_STRIDE + c + 1] = to_tf32(p3);
            O[nj][0] *= al0; O[nj][1] *= al0;
            O[nj][2] *= al1; O[nj][3] *= al1;
        }
        rs0 += __shfl_xor_sync(0xffffffffu, rs0, 1);
        rs0 += __shfl_xor_sync(0xffffffffu, rs0, 2);
        rs1 += __shfl_xor_sync(0xffffffffu, rs1, 1);
        rs1 += __shfl_xor_sync(0xffffffffu, rs1, 2);
        l0 = l0 * al0 + rs0;
        l1 = l1 * al1 + rs1;

        __syncwarp();

        #pragma unroll
        for (int ks = 0; ks < AT_TK; ks += 8) {
            uint32_t a[4];
            a[0] = __float_as_uint(Ps[(mrow + qr    ) * PS_STRIDE + ks + qc    ]);
            a[1] = __float_as_uint(Ps[(mrow + qr + 8) * PS_STRIDE + ks + qc    ]);
            a[2] = __float_as_uint(Ps[(mrow + qr    ) * PS_STRIDE + ks + qc + 4]);
            a[3] = __float_as_uint(Ps[(mrow + qr + 8) * PS_STRIDE + ks + qc + 4]);
            #pragma unroll
            for (int nj = 0; nj < 8; nj++) {
                uint32_t bb[2];
                bb[0] = __float_as_uint(Vs[(ks + qc    ) * VS_STRIDE + nj * 8 + qr]);
                bb[1] = __float_as_uint(Vs[(ks + qc + 4) * VS_STRIDE + nj * 8 + qr]);
                mma_tf32(O[nj], a, bb);
            }
        }
        __syncthreads();
    }

    float inv0 = 1.f / l0, inv1 = 1.f / l1;
    int r0 = mrow + qr, r1 = mrow + qr + 8;
    #pragma unroll
    for (int nj = 0; nj < 8; nj++) {
        int c = h * HDIM + nj * 8 + 2 * qc;
        if (r0 < rows) {
            float* p = outbuf + (size_t)(qrow0 + r0) * D + c;
            p[0] = to_tf32(O[nj][0] * inv0);
            p[1] = to_tf32(O[nj][1] * inv0);
        }
        if (r1 < rows) {
            float* p = outbuf + (size_t)(qrow0 + r1) * D + c;
            p[0] = to_tf32(O[nj][2] * inv1);
            p[1] = to_tf32(O[nj][3] * inv1);
        }
    }
}

// ---------------------------------------------------------------------------
// kernel_launch
// ---------------------------------------------------------------------------
extern "C" void kernel_launch(void* const* d_in, const int* in_sizes, int n_in,
                              void* d_out, int out_size)
{
    const float* hidden = (const float*)d_in[0];
    const float* cross  = (const float*)d_in[1];
    const int*   seqs   = (const int*)d_in[2];
    const float* Wq  = (const float*)d_in[3];
    const float* bq  = (const float*)d_in[4];
    const float* Wkv = (const float*)d_in[5];
    const float* bkv = (const float*)d_in[6];
    const float* Wo  = (const float*)d_in[7];
    const float* bo  = (const float*)d_in[8];
    float* out = (float*)d_out;

    int qlen  = in_sizes[0] / D;
    int kvlen = in_sizes[1] / D;
    int nB    = in_sizes[2];
    int enc   = kvlen / nB;

    float *qbuf, *kvbuf, *abuf, *hidT, *crossT, *wqT, *wkvT, *woT;
    cudaGetSymbolAddress((void**)&qbuf, g_q);
    cudaGetSymbolAddress((void**)&kvbuf, g_kv);
    cudaGetSymbolAddress((void**)&abuf, g_attn);
    cudaGetSymbolAddress((void**)&hidT, g_hid);
    cudaGetSymbolAddress((void**)&crossT, g_cross);
    cudaGetSymbolAddress((void**)&wqT, g_wq);
    cudaGetSymbolAddress((void**)&wkvT, g_wkv);
    cudaGetSymbolAddress((void**)&woT, g_wo);

    cudaFuncSetAttribute(attn_mma_kernel,
                         cudaFuncAttributeMaxDynamicSharedMemorySize, ATTN_SMEM_BYTES);
    cudaFuncSetAttribute(gemm_tf32_cp_kernel,
                         cudaFuncAttributeMaxDynamicSharedMemorySize, GEMM_SMEM_BYTES);

    dim3 blk(256);
    float scaling = 1.0f / sqrtf((float)HDIM);

    // ---- pre-convert all GEMM inputs to tf32 ----
    {
        int n4;
        n4 = in_sizes[0] / 4;
        cvt_tf32_kernel<<<(n4 + 255) / 256, 256>>>(hidden, hidT, n4);
        n4 = in_sizes[1] / 4;
        cvt_tf32_kernel<<<(n4 + 255) / 256, 256>>>(cross, crossT, n4);
        n4 = in_sizes[3] / 4;
        cvt_tf32_kernel<<<(n4 + 255) / 256, 256>>>(Wq, wqT, n4);
        n4 = in_sizes[5] / 4;
        cvt_tf32_kernel<<<(n4 + 255) / 256, 256>>>(Wkv, wkvT, n4);
        n4 = in_sizes[7] / 4;
        cvt_tf32_kernel<<<(n4 + 255) / 256, 256>>>(Wo, woT, n4);
    }

    // Q projection (scaling fused, output rounded for attention)
    gemm_tf32_cp_kernel<<<dim3(D / 128, (qlen + 127) / 128), blk, GEMM_SMEM_BYTES>>>(
        hidT, wqT, bq, qbuf, qlen, D, D, scaling, 1);

    // KV projection (output rounded)
    gemm_tf32_cp_kernel<<<dim3((2 * D) / 128, (kvlen + 127) / 128), blk, GEMM_SMEM_BYTES>>>(
        crossT, wkvT, bkv, kvbuf, kvlen, 2 * D, D, 1.0f, 1);

    // Fused attention (tensor-core; output rounded for O-proj)
    int qtiles = (qlen + AT_TQ - 1) / AT_TQ;
    attn_mma_kernel<<<dim3(H, nB, qtiles), blk, ATTN_SMEM_BYTES>>>(
        qbuf, kvbuf, seqs, abuf, nB, enc);

    // Output projection (full fp32 out)
    gemm_tf32_cp_kernel<<<dim3(D / 128, (qlen + 127) / 128), blk, GEMM_SMEM_BYTES>>>(
        abuf, woT, bo, out, qlen, D, D, 1.0f, 0);
}